// round 2
// baseline (speedup 1.0000x reference)
#include <cuda_runtime.h>
#include <cstdint>
#include <math.h>

// Problem constants (FlaxGrok1SparseMoeBlock: B=2,S=1024 -> T=2048, H=1024, I=4096, E=8, K=2)
#define T_TOKENS 2048
#define HDIM 1024
#define IDIM 4096
#define NEXP 8
#define NPAIR (T_TOKENS * 2)

// ---------------- device scratch (static; no runtime allocation) ----------------
__device__ int   d_counts[NEXP];
__device__ int   d_offsets[NEXP];
__device__ int   d_cursor[NEXP];
__device__ int   d_tok[NPAIR];        // slot -> token index
__device__ float d_wt[NPAIR];         // slot -> routing weight
__device__ int   d_slot[NPAIR];       // token*2+k -> slot
__device__ int   d_te[NPAIR];         // token*2+k -> expert
__device__ float d_tw[NPAIR];         // token*2+k -> weight
__device__ float d_act[(size_t)NPAIR * IDIM];   // activations a = gelu(g)*v  (64 MB)
__device__ float d_yscr[(size_t)NPAIR * HDIM];  // per-slot weighted outputs   (16 MB)

// ---------------- kernel 0: zero expert counters ----------------
__global__ void k_zero() {
    int t = threadIdx.x;
    if (t < NEXP) d_counts[t] = 0;
}

// ---------------- kernel 1: router (logits, top-2, softmax) ----------------
__global__ void k_router(const float* __restrict__ x,
                         const float* __restrict__ Wg,
                         float* __restrict__ logits_out) {
    const int t = blockIdx.x;
    const int tid = threadIdx.x;
    const float* xr = x + (size_t)t * HDIM;

    float acc[NEXP];
#pragma unroll
    for (int e = 0; e < NEXP; e++) acc[e] = 0.f;

    for (int h = tid; h < HDIM; h += 256) {
        float xv = xr[h];
#pragma unroll
        for (int e = 0; e < NEXP; e++) acc[e] += xv * Wg[h * NEXP + e];
    }

    __shared__ float red[256];
    __shared__ float lg[NEXP];
#pragma unroll
    for (int e = 0; e < NEXP; e++) {
        red[tid] = acc[e];
        __syncthreads();
        for (int s = 128; s > 0; s >>= 1) {
            if (tid < s) red[tid] += red[tid + s];
            __syncthreads();
        }
        if (tid == 0) lg[e] = red[0];
        __syncthreads();
    }

    if (tid == 0) {
        int e0 = 0; float l0 = lg[0];
#pragma unroll
        for (int e = 1; e < NEXP; e++) if (lg[e] > l0) { l0 = lg[e]; e0 = e; }
        int e1 = -1; float l1 = -3.4e38f;
#pragma unroll
        for (int e = 0; e < NEXP; e++) if (e != e0 && lg[e] > l1) { l1 = lg[e]; e1 = e; }
        float tt = expf(l1 - l0);
        float w0 = 1.f / (1.f + tt);
        float w1 = tt / (1.f + tt);
        d_te[2 * t] = e0;     d_tw[2 * t] = w0;
        d_te[2 * t + 1] = e1; d_tw[2 * t + 1] = w1;
        atomicAdd(&d_counts[e0], 1);
        atomicAdd(&d_counts[e1], 1);
        if (logits_out) {
#pragma unroll
            for (int e = 0; e < NEXP; e++) logits_out[(size_t)t * NEXP + e] = lg[e];
        }
    }
}

// ---------------- kernel 2: exclusive scan of 8 counts ----------------
__global__ void k_scan() {
    int off = 0;
    for (int e = 0; e < NEXP; e++) {
        d_offsets[e] = off;
        d_cursor[e]  = off;
        off += d_counts[e];
    }
}

// ---------------- kernel 3: scatter token-expert pairs into expert lists ----------------
__global__ void k_scatter() {
    int i = blockIdx.x * blockDim.x + threadIdx.x;
    if (i >= NPAIR) return;
    int e = d_te[i];
    int pos = atomicAdd(&d_cursor[e], 1);
    d_tok[pos] = i >> 1;
    d_wt[pos]  = d_tw[i];
    d_slot[i]  = pos;
}

// ---------------- GELU tanh approx ----------------
__device__ __forceinline__ float gelu_tanh(float g) {
    float c = g + 0.044715f * g * g * g;
    return 0.5f * g * (1.f + tanhf(0.7978845608028654f * c));
}

// ---------------- kernel 4: fused grouped GEMM x@Win, x@Wv -> gelu(g)*v ----------------
// tile: 128 rows x 64 cols, BK=16, 256 threads, 8x4 micro-tile per thread (x2 matrices)
__global__ __launch_bounds__(256)
void k_gemm1(const float* __restrict__ x,
             const float* __restrict__ Win,
             const float* __restrict__ Wv) {
    const int e = blockIdx.z;
    const int cnt = d_counts[e];
    const int m0 = blockIdx.y * 128;
    if (m0 >= cnt) return;
    const int n0 = blockIdx.x * 64;
    const int base = d_offsets[e];
    const int tid = threadIdx.x;
    const int tr = tid >> 4;   // 0..15 (row group)
    const int tc = tid & 15;   // 0..15 (col group)

    __shared__ float As[128][17];
    __shared__ float Bg[16][64];
    __shared__ float Bv[16][64];

    // per-thread gathered row base offsets for the 8 A-load slices
    int arow[8];
#pragma unroll
    for (int l = 0; l < 8; l++) {
        int m = l * 16 + (tid >> 4);
        int gm = m0 + m;
        arow[l] = (gm < cnt) ? d_tok[base + gm] * HDIM : -1;
    }
    const int ak = tid & 15;
    const int bk = tid >> 4;
    const int bn = (tid & 15) * 4;

    float accg[8][4], accv[8][4];
#pragma unroll
    for (int i = 0; i < 8; i++)
#pragma unroll
        for (int j = 0; j < 4; j++) { accg[i][j] = 0.f; accv[i][j] = 0.f; }

    for (int k0 = 0; k0 < HDIM; k0 += 16) {
#pragma unroll
        for (int l = 0; l < 8; l++) {
            int m = l * 16 + (tid >> 4);
            As[m][ak] = (arow[l] >= 0) ? x[arow[l] + k0 + ak] : 0.f;
        }
        {
            size_t goff = ((size_t)e * HDIM + (k0 + bk)) * IDIM + n0 + bn;
            float4 vg = *(const float4*)(Win + goff);
            float4 vv = *(const float4*)(Wv + goff);
            *(float4*)&Bg[bk][bn] = vg;
            *(float4*)&Bv[bk][bn] = vv;
        }
        __syncthreads();
#pragma unroll
        for (int kk = 0; kk < 16; kk++) {
            float a[8];
#pragma unroll
            for (int i = 0; i < 8; i++) a[i] = As[tr * 8 + i][kk];
            float4 bg4 = *(const float4*)&Bg[kk][tc * 4];
            float4 bv4 = *(const float4*)&Bv[kk][tc * 4];
            float bg[4] = {bg4.x, bg4.y, bg4.z, bg4.w};
            float bv[4] = {bv4.x, bv4.y, bv4.z, bv4.w};
#pragma unroll
            for (int i = 0; i < 8; i++)
#pragma unroll
                for (int j = 0; j < 4; j++) {
                    accg[i][j] += a[i] * bg[j];
                    accv[i][j] += a[i] * bv[j];
                }
        }
        __syncthreads();
    }

#pragma unroll
    for (int i = 0; i < 8; i++) {
        int gm = m0 + tr * 8 + i;
        if (gm >= cnt) continue;
        size_t rowoff = (size_t)(base + gm) * IDIM + n0 + tc * 4;
#pragma unroll
        for (int j = 0; j < 4; j++) {
            d_act[rowoff + j] = gelu_tanh(accg[i][j]) * accv[i][j];
        }
    }
}

// ---------------- kernel 5: grouped GEMM a@Wout, scaled by routing weight ----------------
__global__ __launch_bounds__(256)
void k_gemm2(const float* __restrict__ Wout) {
    const int e = blockIdx.z;
    const int cnt = d_counts[e];
    const int m0 = blockIdx.y * 128;
    if (m0 >= cnt) return;
    const int n0 = blockIdx.x * 64;
    const int base = d_offsets[e];
    const int tid = threadIdx.x;
    const int tr = tid >> 4;
    const int tc = tid & 15;

    __shared__ float As[128][17];
    __shared__ float Bs[16][64];

    const int ak = tid & 15;
    const int bk = tid >> 4;
    const int bn = (tid & 15) * 4;

    // A rows are contiguous in d_act
    long arow[8];
#pragma unroll
    for (int l = 0; l < 8; l++) {
        int m = l * 16 + (tid >> 4);
        int gm = m0 + m;
        arow[l] = (gm < cnt) ? (long)((size_t)(base + gm) * IDIM) : -1;
    }

    float acc[8][4];
#pragma unroll
    for (int i = 0; i < 8; i++)
#pragma unroll
        for (int j = 0; j < 4; j++) acc[i][j] = 0.f;

    for (int k0 = 0; k0 < IDIM; k0 += 16) {
#pragma unroll
        for (int l = 0; l < 8; l++) {
            int m = l * 16 + (tid >> 4);
            As[m][ak] = (arow[l] >= 0) ? d_act[arow[l] + k0 + ak] : 0.f;
        }
        {
            size_t goff = ((size_t)e * IDIM + (k0 + bk)) * HDIM + n0 + bn;
            *(float4*)&Bs[bk][bn] = *(const float4*)(Wout + goff);
        }
        __syncthreads();
#pragma unroll
        for (int kk = 0; kk < 16; kk++) {
            float a[8];
#pragma unroll
            for (int i = 0; i < 8; i++) a[i] = As[tr * 8 + i][kk];
            float4 b4 = *(const float4*)&Bs[kk][tc * 4];
            float b[4] = {b4.x, b4.y, b4.z, b4.w};
#pragma unroll
            for (int i = 0; i < 8; i++)
#pragma unroll
                for (int j = 0; j < 4; j++) acc[i][j] += a[i] * b[j];
        }
        __syncthreads();
    }

#pragma unroll
    for (int i = 0; i < 8; i++) {
        int gm = m0 + tr * 8 + i;
        if (gm >= cnt) continue;
        float wt = d_wt[base + gm];
        size_t rowoff = (size_t)(base + gm) * HDIM + n0 + tc * 4;
#pragma unroll
        for (int j = 0; j < 4; j++) {
            d_yscr[rowoff + j] = acc[i][j] * wt;
        }
    }
}

// ---------------- kernel 6: combine the two expert outputs per token ----------------
__global__ void k_combine(float* __restrict__ out) {
    const int t = blockIdx.x;
    const int s0 = d_slot[2 * t];
    const int s1 = d_slot[2 * t + 1];
    const float* y0 = d_yscr + (size_t)s0 * HDIM;
    const float* y1 = d_yscr + (size_t)s1 * HDIM;
    float* o = out + (size_t)t * HDIM;
    for (int h = threadIdx.x; h < HDIM; h += 256) {
        o[h] = y0[h] + y1[h];
    }
}

// ---------------- launch ----------------
extern "C" void kernel_launch(void* const* d_in, const int* in_sizes, int n_in,
                              void* d_out, int out_size) {
    const float* x    = (const float*)d_in[0];
    const float* Wg   = (const float*)d_in[1];
    const float* Win  = (const float*)d_in[2];
    const float* Wv   = (const float*)d_in[3];
    const float* Wout = (const float*)d_in[4];
    float* out = (float*)d_out;

    float* logits = nullptr;
    if (out_size >= (int)((size_t)T_TOKENS * HDIM + (size_t)T_TOKENS * NEXP))
        logits = out + (size_t)T_TOKENS * HDIM;

    k_zero<<<1, 32>>>();
    k_router<<<T_TOKENS, 256>>>(x, Wg, logits);
    k_scan<<<1, 1>>>();
    k_scatter<<<NPAIR / 256, 256>>>();

    dim3 g1(IDIM / 64, (T_TOKENS + 127) / 128, NEXP);
    k_gemm1<<<g1, 256>>>(x, Win, Wv);

    dim3 g2(HDIM / 64, (T_TOKENS + 127) / 128, NEXP);
    k_gemm2<<<g2, 256>>>(Wout);

    k_combine<<<T_TOKENS, 256>>>(out);
}

// round 3
// speedup vs baseline: 3.1068x; 3.1068x over previous
#include <cuda_runtime.h>
#include <cstdint>
#include <math.h>

// Problem constants (FlaxGrok1SparseMoeBlock: B=2,S=1024 -> T=2048, H=1024, I=4096, E=8, K=2)
#define T_TOKENS 2048
#define HDIM 1024
#define IDIM 4096
#define NEXP 8
#define NPAIR (T_TOKENS * 2)

// ---------------- device scratch (static; no runtime allocation) ----------------
__device__ int   d_counts[NEXP];
__device__ int   d_offsets[NEXP];
__device__ int   d_cursor[NEXP];
__device__ int   d_tok[NPAIR];        // slot -> token index
__device__ float d_wt[NPAIR];         // slot -> routing weight
__device__ int   d_slot[NPAIR];       // token*2+k -> slot
__device__ int   d_te[NPAIR];         // token*2+k -> expert
__device__ float d_tw[NPAIR];         // token*2+k -> weight
__device__ float d_act[(size_t)NPAIR * IDIM];   // activations a = gelu(g)*v  (64 MB)
__device__ float d_yscr[(size_t)NPAIR * HDIM];  // per-slot weighted outputs   (16 MB)

// ---------------- helpers ----------------
__device__ __forceinline__ uint32_t f2tf(float f) {
    uint32_t u;
    asm("cvt.rna.tf32.f32 %0, %1;" : "=r"(u) : "f"(f));
    return u;
}

__device__ __forceinline__ void mma_tf32(float c[4], const uint32_t a[4], const uint32_t b[2]) {
    asm volatile(
        "mma.sync.aligned.m16n8k8.row.col.f32.tf32.tf32.f32 "
        "{%0,%1,%2,%3}, {%4,%5,%6,%7}, {%8,%9}, {%0,%1,%2,%3};"
        : "+f"(c[0]), "+f"(c[1]), "+f"(c[2]), "+f"(c[3])
        : "r"(a[0]), "r"(a[1]), "r"(a[2]), "r"(a[3]), "r"(b[0]), "r"(b[1]));
}

__device__ __forceinline__ float gelu_tanh(float g) {
    float c = g + 0.044715f * g * g * g;
    return 0.5f * g * (1.f + tanhf(0.7978845608028654f * c));
}

// ---------------- kernel 0: zero expert counters ----------------
__global__ void k_zero() {
    int t = threadIdx.x;
    if (t < NEXP) d_counts[t] = 0;
}

// ---------------- kernel 1: router (logits, top-2, softmax) ----------------
__global__ void k_router(const float* __restrict__ x,
                         const float* __restrict__ Wg,
                         float* __restrict__ logits_out) {
    const int t = blockIdx.x;
    const int tid = threadIdx.x;
    const float* xr = x + (size_t)t * HDIM;

    float acc[NEXP];
#pragma unroll
    for (int e = 0; e < NEXP; e++) acc[e] = 0.f;

    for (int h = tid; h < HDIM; h += 256) {
        float xv = xr[h];
#pragma unroll
        for (int e = 0; e < NEXP; e++) acc[e] += xv * Wg[h * NEXP + e];
    }

    __shared__ float red[256];
    __shared__ float lg[NEXP];
#pragma unroll
    for (int e = 0; e < NEXP; e++) {
        red[tid] = acc[e];
        __syncthreads();
        for (int s = 128; s > 0; s >>= 1) {
            if (tid < s) red[tid] += red[tid + s];
            __syncthreads();
        }
        if (tid == 0) lg[e] = red[0];
        __syncthreads();
    }

    if (tid == 0) {
        int e0 = 0; float l0 = lg[0];
#pragma unroll
        for (int e = 1; e < NEXP; e++) if (lg[e] > l0) { l0 = lg[e]; e0 = e; }
        int e1 = -1; float l1 = -3.4e38f;
#pragma unroll
        for (int e = 0; e < NEXP; e++) if (e != e0 && lg[e] > l1) { l1 = lg[e]; e1 = e; }
        float tt = expf(l1 - l0);
        float w0 = 1.f / (1.f + tt);
        float w1 = tt / (1.f + tt);
        d_te[2 * t] = e0;     d_tw[2 * t] = w0;
        d_te[2 * t + 1] = e1; d_tw[2 * t + 1] = w1;
        atomicAdd(&d_counts[e0], 1);
        atomicAdd(&d_counts[e1], 1);
        if (logits_out) {
#pragma unroll
            for (int e = 0; e < NEXP; e++) logits_out[(size_t)t * NEXP + e] = lg[e];
        }
    }
}

// ---------------- kernel 2: exclusive scan of 8 counts ----------------
__global__ void k_scan() {
    int off = 0;
    for (int e = 0; e < NEXP; e++) {
        d_offsets[e] = off;
        d_cursor[e]  = off;
        off += d_counts[e];
    }
}

// ---------------- kernel 3: scatter token-expert pairs into expert lists ----------------
__global__ void k_scatter() {
    int i = blockIdx.x * blockDim.x + threadIdx.x;
    if (i >= NPAIR) return;
    int e = d_te[i];
    int pos = atomicAdd(&d_cursor[e], 1);
    d_tok[pos] = i >> 1;
    d_wt[pos]  = d_tw[i];
    d_slot[i]  = pos;
}

// =====================================================================
// kernel 4: fused grouped GEMM (TF32 tensor cores)
//   g = x@Win[e], v = x@Wv[e], act = gelu(g)*v
//   tile: BM=128, BN=64 (per matrix), BK=16; 8 warps (4x2), warp tile 32x32
// =====================================================================
__global__ __launch_bounds__(256, 2)
void k_gemm1(const float* __restrict__ x,
             const float* __restrict__ Win,
             const float* __restrict__ Wv) {
    const int e = blockIdx.z;
    const int cnt = d_counts[e];
    const int m0 = blockIdx.y * 128;
    if (m0 >= cnt) return;
    const int n0 = blockIdx.x * 64;
    const int base = d_offsets[e];
    const int tid = threadIdx.x;
    const int lane = tid & 31;
    const int wid = tid >> 5;
    const int wm = (wid & 3) * 32;   // warp M offset within tile
    const int wn = (wid >> 2) * 32;  // warp N offset within tile
    const int gid = lane >> 2;
    const int t4 = lane & 3;

    __shared__ uint32_t As[128][20];  // stride 20 -> conflict-free, 16B aligned
    __shared__ uint32_t Bg[16][72];   // stride 72 -> conflict-free, 16B aligned
    __shared__ uint32_t Bv[16][72];

    // A load mapping: 512 float4 = 2 per thread; row = (tid>>2)+l*64, kq = (tid&3)*4
    int toks[2];
#pragma unroll
    for (int l = 0; l < 2; l++) {
        int row = (tid >> 2) + l * 64;
        int gm = m0 + row;
        int idx = base + (gm < cnt ? gm : cnt - 1);
        toks[l] = d_tok[idx];
    }
    const int a_kq = (tid & 3) * 4;
    const int b_row = tid >> 4;          // 0..15
    const int b_col = (tid & 15) * 4;    // 0..60

    float accg[2][4][4], accv[2][4][4];
#pragma unroll
    for (int i = 0; i < 2; i++)
#pragma unroll
        for (int j = 0; j < 4; j++)
#pragma unroll
            for (int q = 0; q < 4; q++) { accg[i][j][q] = 0.f; accv[i][j][q] = 0.f; }

    for (int k0 = 0; k0 < HDIM; k0 += 16) {
        // load A (gathered token rows), convert to tf32
#pragma unroll
        for (int l = 0; l < 2; l++) {
            int row = (tid >> 2) + l * 64;
            float4 v = *(const float4*)(x + (size_t)toks[l] * HDIM + k0 + a_kq);
            uint4 t; t.x = f2tf(v.x); t.y = f2tf(v.y); t.z = f2tf(v.z); t.w = f2tf(v.w);
            *(uint4*)&As[row][a_kq] = t;
        }
        // load B tiles (Win, Wv)
        {
            size_t goff = ((size_t)e * HDIM + (k0 + b_row)) * IDIM + n0 + b_col;
            float4 vg = *(const float4*)(Win + goff);
            float4 vv = *(const float4*)(Wv + goff);
            uint4 tg; tg.x = f2tf(vg.x); tg.y = f2tf(vg.y); tg.z = f2tf(vg.z); tg.w = f2tf(vg.w);
            uint4 tv; tv.x = f2tf(vv.x); tv.y = f2tf(vv.y); tv.z = f2tf(vv.z); tv.w = f2tf(vv.w);
            *(uint4*)&Bg[b_row][b_col] = tg;
            *(uint4*)&Bv[b_row][b_col] = tv;
        }
        __syncthreads();

#pragma unroll
        for (int kk = 0; kk < 16; kk += 8) {
            uint32_t af[2][4];
#pragma unroll
            for (int mt = 0; mt < 2; mt++) {
                int r = wm + mt * 16 + gid;
                af[mt][0] = As[r][kk + t4];
                af[mt][1] = As[r + 8][kk + t4];
                af[mt][2] = As[r][kk + t4 + 4];
                af[mt][3] = As[r + 8][kk + t4 + 4];
            }
#pragma unroll
            for (int nt = 0; nt < 4; nt++) {
                int c = wn + nt * 8 + gid;
                uint32_t bg[2] = { Bg[kk + t4][c], Bg[kk + t4 + 4][c] };
                uint32_t bv[2] = { Bv[kk + t4][c], Bv[kk + t4 + 4][c] };
#pragma unroll
                for (int mt = 0; mt < 2; mt++) {
                    mma_tf32(accg[mt][nt], af[mt], bg);
                    mma_tf32(accv[mt][nt], af[mt], bv);
                }
            }
        }
        __syncthreads();
    }

    // epilogue: act = gelu(g)*v
#pragma unroll
    for (int mt = 0; mt < 2; mt++) {
#pragma unroll
        for (int nt = 0; nt < 4; nt++) {
            int col = n0 + wn + nt * 8 + t4 * 2;
#pragma unroll
            for (int h = 0; h < 2; h++) {
                int gm = m0 + wm + mt * 16 + gid + h * 8;
                if (gm < cnt) {
                    size_t off = (size_t)(base + gm) * IDIM + col;
                    float g0 = accg[mt][nt][h * 2],     g1 = accg[mt][nt][h * 2 + 1];
                    float v0 = accv[mt][nt][h * 2],     v1 = accv[mt][nt][h * 2 + 1];
                    float2 r; r.x = gelu_tanh(g0) * v0; r.y = gelu_tanh(g1) * v1;
                    *(float2*)(d_act + off) = r;
                }
            }
        }
    }
}

// =====================================================================
// kernel 5: grouped GEMM #2 (TF32): y = act@Wout[e], scaled by routing wt
//   tile: BM=128, BN=128, BK=16; 8 warps (4x2), warp tile 32x64
// =====================================================================
__global__ __launch_bounds__(256, 2)
void k_gemm2(const float* __restrict__ Wout) {
    const int e = blockIdx.z;
    const int cnt = d_counts[e];
    const int m0 = blockIdx.y * 128;
    if (m0 >= cnt) return;
    const int n0 = blockIdx.x * 128;
    const int base = d_offsets[e];
    const int tid = threadIdx.x;
    const int lane = tid & 31;
    const int wid = tid >> 5;
    const int wm = (wid & 3) * 32;
    const int wn = (wid >> 2) * 64;
    const int gid = lane >> 2;
    const int t4 = lane & 3;

    __shared__ uint32_t As[128][20];
    __shared__ uint32_t Bs[16][136];  // stride 136 -> conflict-free, 16B aligned

    // A rows are contiguous in d_act; clamp OOB row index
    size_t arow[2];
#pragma unroll
    for (int l = 0; l < 2; l++) {
        int row = (tid >> 2) + l * 64;
        int gm = m0 + row;
        int idx = base + gm;
        if (idx > NPAIR - 1) idx = NPAIR - 1;
        arow[l] = (size_t)idx * IDIM;
    }
    const int a_kq = (tid & 3) * 4;

    float acc[2][8][4];
#pragma unroll
    for (int i = 0; i < 2; i++)
#pragma unroll
        for (int j = 0; j < 8; j++)
#pragma unroll
            for (int q = 0; q < 4; q++) acc[i][j][q] = 0.f;

    for (int k0 = 0; k0 < IDIM; k0 += 16) {
#pragma unroll
        for (int l = 0; l < 2; l++) {
            int row = (tid >> 2) + l * 64;
            float4 v = *(const float4*)(d_act + arow[l] + k0 + a_kq);
            uint4 t; t.x = f2tf(v.x); t.y = f2tf(v.y); t.z = f2tf(v.z); t.w = f2tf(v.w);
            *(uint4*)&As[row][a_kq] = t;
        }
#pragma unroll
        for (int l = 0; l < 2; l++) {
            int lin = tid + l * 256;
            int row = lin >> 5;          // 0..15
            int col = (lin & 31) * 4;    // 0..124
            size_t goff = ((size_t)e * IDIM + (k0 + row)) * HDIM + n0 + col;
            float4 v = *(const float4*)(Wout + goff);
            uint4 t; t.x = f2tf(v.x); t.y = f2tf(v.y); t.z = f2tf(v.z); t.w = f2tf(v.w);
            *(uint4*)&Bs[row][col] = t;
        }
        __syncthreads();

#pragma unroll
        for (int kk = 0; kk < 16; kk += 8) {
            uint32_t af[2][4];
#pragma unroll
            for (int mt = 0; mt < 2; mt++) {
                int r = wm + mt * 16 + gid;
                af[mt][0] = As[r][kk + t4];
                af[mt][1] = As[r + 8][kk + t4];
                af[mt][2] = As[r][kk + t4 + 4];
                af[mt][3] = As[r + 8][kk + t4 + 4];
            }
#pragma unroll
            for (int nt = 0; nt < 8; nt++) {
                int c = wn + nt * 8 + gid;
                uint32_t bf[2] = { Bs[kk + t4][c], Bs[kk + t4 + 4][c] };
#pragma unroll
                for (int mt = 0; mt < 2; mt++) {
                    mma_tf32(acc[mt][nt], af[mt], bf);
                }
            }
        }
        __syncthreads();
    }

#pragma unroll
    for (int mt = 0; mt < 2; mt++) {
#pragma unroll
        for (int nt = 0; nt < 8; nt++) {
            int col = n0 + wn + nt * 8 + t4 * 2;
#pragma unroll
            for (int h = 0; h < 2; h++) {
                int gm = m0 + wm + mt * 16 + gid + h * 8;
                if (gm < cnt) {
                    float wt = d_wt[base + gm];
                    size_t off = (size_t)(base + gm) * HDIM + col;
                    float2 r;
                    r.x = acc[mt][nt][h * 2] * wt;
                    r.y = acc[mt][nt][h * 2 + 1] * wt;
                    *(float2*)(d_yscr + off) = r;
                }
            }
        }
    }
}

// ---------------- kernel 6: combine the two expert outputs per token ----------------
__global__ void k_combine(float* __restrict__ out) {
    const int t = blockIdx.x;
    const int s0 = d_slot[2 * t];
    const int s1 = d_slot[2 * t + 1];
    const float* y0 = d_yscr + (size_t)s0 * HDIM;
    const float* y1 = d_yscr + (size_t)s1 * HDIM;
    float* o = out + (size_t)t * HDIM;
    for (int h = threadIdx.x; h < HDIM; h += 256) {
        o[h] = y0[h] + y1[h];
    }
}

// ---------------- launch ----------------
extern "C" void kernel_launch(void* const* d_in, const int* in_sizes, int n_in,
                              void* d_out, int out_size) {
    const float* x    = (const float*)d_in[0];
    const float* Wg   = (const float*)d_in[1];
    const float* Win  = (const float*)d_in[2];
    const float* Wv   = (const float*)d_in[3];
    const float* Wout = (const float*)d_in[4];
    float* out = (float*)d_out;

    float* logits = nullptr;
    if (out_size >= (int)((size_t)T_TOKENS * HDIM + (size_t)T_TOKENS * NEXP))
        logits = out + (size_t)T_TOKENS * HDIM;

    k_zero<<<1, 32>>>();
    k_router<<<T_TOKENS, 256>>>(x, Wg, logits);
    k_scan<<<1, 1>>>();
    k_scatter<<<NPAIR / 256, 256>>>();

    dim3 g1(IDIM / 64, (T_TOKENS + 127) / 128, NEXP);
    k_gemm1<<<g1, 256>>>(x, Win, Wv);

    dim3 g2(HDIM / 128, (T_TOKENS + 127) / 128, NEXP);
    k_gemm2<<<g2, 256>>>(Wout);

    k_combine<<<T_TOKENS, 256>>>(out);
}

// round 5
// speedup vs baseline: 4.2053x; 1.3536x over previous
#include <cuda_runtime.h>
#include <cuda_fp16.h>
#include <cstdint>
#include <math.h>

// Problem constants (FlaxGrok1SparseMoeBlock: B=2,S=1024 -> T=2048, H=1024, I=4096, E=8, K=2)
#define T_TOKENS 2048
#define HDIM 1024
#define IDIM 4096
#define NEXP 8
#define NPAIR (T_TOKENS * 2)

// ---------------- device scratch (static; no runtime allocation) ----------------
__device__ int    d_counts[NEXP];
__device__ int    d_offsets[NEXP];
__device__ int    d_cursor[NEXP];
__device__ int    d_tok[NPAIR];
__device__ float  d_wt[NPAIR];
__device__ int    d_slot[NPAIR];
__device__ int    d_te[NPAIR];
__device__ float  d_tw[NPAIR];
__device__ __half d_act_h[(size_t)NPAIR * IDIM];  // 32 MB (half)
__device__ float  d_yscr[(size_t)NPAIR * HDIM];   // 16 MB

// ---------------- helpers ----------------
__device__ __forceinline__ uint32_t packh2(float lo, float hi) {
    __half2 h = __floats2half2_rn(lo, hi);
    return *(uint32_t*)&h;
}
__device__ __forceinline__ void mma_f16(float c[4], const uint32_t a[4], const uint32_t b[2]) {
    asm volatile(
        "mma.sync.aligned.m16n8k16.row.col.f32.f16.f16.f32 "
        "{%0,%1,%2,%3}, {%4,%5,%6,%7}, {%8,%9}, {%0,%1,%2,%3};"
        : "+f"(c[0]), "+f"(c[1]), "+f"(c[2]), "+f"(c[3])
        : "r"(a[0]), "r"(a[1]), "r"(a[2]), "r"(a[3]), "r"(b[0]), "r"(b[1]));
}
__device__ __forceinline__ float gelu_tanh(float g) {
    float c = g + 0.044715f * g * g * g;
    return 0.5f * g * (1.f + tanhf(0.7978845608028654f * c));
}

// ---------------- kernel 0..3: routing ----------------
__global__ void k_zero() { if (threadIdx.x < NEXP) d_counts[threadIdx.x] = 0; }

__global__ void k_router(const float* __restrict__ x, const float* __restrict__ Wg,
                         float* __restrict__ logits_out) {
    const int t = blockIdx.x;
    const int tid = threadIdx.x;
    const float* xr = x + (size_t)t * HDIM;
    float acc[NEXP];
#pragma unroll
    for (int e = 0; e < NEXP; e++) acc[e] = 0.f;
    for (int h = tid; h < HDIM; h += 256) {
        float xv = xr[h];
#pragma unroll
        for (int e = 0; e < NEXP; e++) acc[e] += xv * Wg[h * NEXP + e];
    }
    __shared__ float red[256];
    __shared__ float lg[NEXP];
#pragma unroll
    for (int e = 0; e < NEXP; e++) {
        red[tid] = acc[e];
        __syncthreads();
        for (int s = 128; s > 0; s >>= 1) { if (tid < s) red[tid] += red[tid + s]; __syncthreads(); }
        if (tid == 0) lg[e] = red[0];
        __syncthreads();
    }
    if (tid == 0) {
        int e0 = 0; float l0 = lg[0];
#pragma unroll
        for (int e = 1; e < NEXP; e++) if (lg[e] > l0) { l0 = lg[e]; e0 = e; }
        int e1 = -1; float l1 = -3.4e38f;
#pragma unroll
        for (int e = 0; e < NEXP; e++) if (e != e0 && lg[e] > l1) { l1 = lg[e]; e1 = e; }
        float tt = expf(l1 - l0);
        float w0 = 1.f / (1.f + tt), w1 = tt / (1.f + tt);
        d_te[2 * t] = e0;     d_tw[2 * t] = w0;
        d_te[2 * t + 1] = e1; d_tw[2 * t + 1] = w1;
        atomicAdd(&d_counts[e0], 1);
        atomicAdd(&d_counts[e1], 1);
        if (logits_out) {
#pragma unroll
            for (int e = 0; e < NEXP; e++) logits_out[(size_t)t * NEXP + e] = lg[e];
        }
    }
}

__global__ void k_scan() {
    int off = 0;
    for (int e = 0; e < NEXP; e++) { d_offsets[e] = off; d_cursor[e] = off; off += d_counts[e]; }
}

__global__ void k_scatter() {
    int i = blockIdx.x * blockDim.x + threadIdx.x;
    if (i >= NPAIR) return;
    int e = d_te[i];
    int pos = atomicAdd(&d_cursor[e], 1);
    d_tok[pos] = i >> 1;
    d_wt[pos]  = d_tw[i];
    d_slot[i]  = pos;
}

// =====================================================================
// GEMM1 (fp16 mma.sync m16n8k16): g=x@Win[e], v=x@Wv[e], act=gelu(g)*v
//   BM=128, BN=64 (per matrix, x2), BK=32; 256 threads; warp tile 32x32
//   3-stage smem pipeline, register prefetch (LDG 2-ahead, STS 1-ahead)
//   smem stage (u32): A[128][20]=2560, Bg[16][72]=1152, Bv=1152 -> 4864
// =====================================================================
#define NCH1 32
#define G1_STG 4864
#define G1_BG  2560
#define G1_BV  3712
#define SM1_BYTES (3 * G1_STG * 4)

__global__ __launch_bounds__(256, 1)
void k_gemm1(const float* __restrict__ x, const float* __restrict__ Win,
             const float* __restrict__ Wv) {
    extern __shared__ uint32_t sm[];
    const int e = blockIdx.z;
    const int cnt = d_counts[e];
    const int m0 = blockIdx.y * 128;
    if (m0 >= cnt) return;
    const int n0 = blockIdx.x * 64;
    const int base = d_offsets[e];
    const int tid = threadIdx.x, lane = tid & 31, wid = tid >> 5;
    const int gid = lane >> 2, t4 = lane & 3;
    const int wm = (wid & 3) * 32, wn = (wid >> 2) * 32;

    // fill mappings
    const int arow = tid >> 1, khalf = tid & 1;
    int gm_a = m0 + arow;
    const float* xrow = x + (size_t)d_tok[base + (gm_a < cnt ? gm_a : cnt - 1)] * HDIM + khalf * 16;
    const int kp = tid >> 4;               // 0..15
    const int nb4 = (tid & 15) * 4;        // 0..60
    const float* wg0 = Win + ((size_t)e * HDIM + 2 * kp) * IDIM + n0 + nb4;
    const float* wv0 = Wv  + ((size_t)e * HDIM + 2 * kp) * IDIM + n0 + nb4;

    float4 pA[4], pG0, pG1, pV0, pV1;

#define G1_LD(c) do { \
        const float* xr_ = xrow + (c) * 32; \
        pA[0] = *(const float4*)(xr_);      pA[1] = *(const float4*)(xr_ + 4); \
        pA[2] = *(const float4*)(xr_ + 8);  pA[3] = *(const float4*)(xr_ + 12); \
        const float* g_ = wg0 + (size_t)(c) * 32 * IDIM; \
        pG0 = *(const float4*)(g_); pG1 = *(const float4*)(g_ + IDIM); \
        const float* v_ = wv0 + (size_t)(c) * 32 * IDIM; \
        pV0 = *(const float4*)(v_); pV1 = *(const float4*)(v_ + IDIM); \
    } while (0)

#define G1_ST(s) do { \
        uint32_t* A_ = sm + (s) * G1_STG; \
        uint4 ua0, ua1; \
        ua0.x = packh2(pA[0].x, pA[0].y); ua0.y = packh2(pA[0].z, pA[0].w); \
        ua0.z = packh2(pA[1].x, pA[1].y); ua0.w = packh2(pA[1].z, pA[1].w); \
        ua1.x = packh2(pA[2].x, pA[2].y); ua1.y = packh2(pA[2].z, pA[2].w); \
        ua1.z = packh2(pA[3].x, pA[3].y); ua1.w = packh2(pA[3].z, pA[3].w); \
        *(uint4*)(A_ + arow * 20 + khalf * 8)     = ua0; \
        *(uint4*)(A_ + arow * 20 + khalf * 8 + 4) = ua1; \
        uint32_t* Bg_ = sm + (s) * G1_STG + G1_BG; \
        uint4 tg; tg.x = packh2(pG0.x, pG1.x); tg.y = packh2(pG0.y, pG1.y); \
                  tg.z = packh2(pG0.z, pG1.z); tg.w = packh2(pG0.w, pG1.w); \
        *(uint4*)(Bg_ + kp * 72 + nb4) = tg; \
        uint32_t* Bv_ = sm + (s) * G1_STG + G1_BV; \
        uint4 tv; tv.x = packh2(pV0.x, pV1.x); tv.y = packh2(pV0.y, pV1.y); \
                  tv.z = packh2(pV0.z, pV1.z); tv.w = packh2(pV0.w, pV1.w); \
        *(uint4*)(Bv_ + kp * 72 + nb4) = tv; \
    } while (0)

    float accg[2][4][4], accv[2][4][4];
#pragma unroll
    for (int i = 0; i < 2; i++)
#pragma unroll
        for (int j = 0; j < 4; j++)
#pragma unroll
            for (int q = 0; q < 4; q++) { accg[i][j][q] = 0.f; accv[i][j][q] = 0.f; }

    G1_LD(0); G1_ST(0); G1_LD(1);
    __syncthreads();

    for (int c = 0; c < NCH1; c++) {
        if (c + 1 < NCH1) G1_ST((c + 1) % 3);
        if (c + 2 < NCH1) G1_LD(c + 2);
        __syncthreads();
        const uint32_t* A_ = sm + (c % 3) * G1_STG;
        const uint32_t* Bg_ = A_ + G1_BG;
        const uint32_t* Bv_ = A_ + G1_BV;
#pragma unroll
        for (int s = 0; s < 2; s++) {
            uint32_t af[2][4];
#pragma unroll
            for (int mt = 0; mt < 2; mt++) {
                int r = wm + mt * 16 + gid;
                af[mt][0] = A_[r * 20 + s * 8 + t4];
                af[mt][1] = A_[(r + 8) * 20 + s * 8 + t4];
                af[mt][2] = A_[r * 20 + s * 8 + t4 + 4];
                af[mt][3] = A_[(r + 8) * 20 + s * 8 + t4 + 4];
            }
#pragma unroll
            for (int nt = 0; nt < 4; nt++) {
                int cidx = wn + nt * 8 + gid;
                uint32_t bg[2] = { Bg_[(s * 8 + t4) * 72 + cidx], Bg_[(s * 8 + t4 + 4) * 72 + cidx] };
                uint32_t bv[2] = { Bv_[(s * 8 + t4) * 72 + cidx], Bv_[(s * 8 + t4 + 4) * 72 + cidx] };
#pragma unroll
                for (int mt = 0; mt < 2; mt++) {
                    mma_f16(accg[mt][nt], af[mt], bg);
                    mma_f16(accv[mt][nt], af[mt], bv);
                }
            }
        }
    }

    // epilogue: act = gelu(g)*v -> half
#pragma unroll
    for (int mt = 0; mt < 2; mt++) {
#pragma unroll
        for (int nt = 0; nt < 4; nt++) {
            int col = n0 + wn + nt * 8 + t4 * 2;
#pragma unroll
            for (int h = 0; h < 2; h++) {
                int gm = m0 + wm + mt * 16 + gid + h * 8;
                if (gm < cnt) {
                    float a0 = gelu_tanh(accg[mt][nt][h * 2])     * accv[mt][nt][h * 2];
                    float a1 = gelu_tanh(accg[mt][nt][h * 2 + 1]) * accv[mt][nt][h * 2 + 1];
                    *(uint32_t*)(d_act_h + (size_t)(base + gm) * IDIM + col) = packh2(a0, a1);
                }
            }
        }
    }
#undef G1_LD
#undef G1_ST
}

// =====================================================================
// GEMM2 (fp16 mma.sync): y = act@Wout[e] * wt
//   BM=128, BN=128, BK=32; 256 threads; warp tile 32x64
//   smem stage (u32): A[128][20]=2560, B[16][136]=2176 -> 4736
// =====================================================================
#define NCH2 128
#define G2_STG 4736
#define G2_B   2560
#define SM2_BYTES (3 * G2_STG * 4)

__global__ __launch_bounds__(256, 1)
void k_gemm2(const float* __restrict__ Wout) {
    extern __shared__ uint32_t sm[];
    const int e = blockIdx.z;
    const int cnt = d_counts[e];
    const int m0 = blockIdx.y * 128;
    if (m0 >= cnt) return;
    const int n0 = blockIdx.x * 128;
    const int base = d_offsets[e];
    const int tid = threadIdx.x, lane = tid & 31, wid = tid >> 5;
    const int gid = lane >> 2, t4 = lane & 3;
    const int wm = (wid & 3) * 32, wn = (wid >> 2) * 64;

    const int arow = tid >> 1, khalf = tid & 1;
    int gm_a = m0 + arow;
    int slot_a = base + gm_a;
    if (slot_a > NPAIR - 1) slot_a = NPAIR - 1;
    const __half* actrow = d_act_h + (size_t)slot_a * IDIM + khalf * 16;

    const int kp = tid >> 4;               // 0..15
    const int nb8 = (tid & 15) * 8;        // 0..120
    const float* w0 = Wout + ((size_t)e * IDIM + 2 * kp) * HDIM + n0 + nb8;

    uint4 pA0, pA1;
    float4 pB00, pB01, pB10, pB11;

#define G2_LD(c) do { \
        const __half* ar_ = actrow + (c) * 32; \
        pA0 = *(const uint4*)(ar_); pA1 = *(const uint4*)(ar_ + 8); \
        const float* wr_ = w0 + (size_t)(c) * 32 * HDIM; \
        pB00 = *(const float4*)(wr_);        pB01 = *(const float4*)(wr_ + 4); \
        pB10 = *(const float4*)(wr_ + HDIM); pB11 = *(const float4*)(wr_ + HDIM + 4); \
    } while (0)

#define G2_ST(s) do { \
        uint32_t* A_ = sm + (s) * G2_STG; \
        *(uint4*)(A_ + arow * 20 + khalf * 8)     = pA0; \
        *(uint4*)(A_ + arow * 20 + khalf * 8 + 4) = pA1; \
        uint32_t* B_ = sm + (s) * G2_STG + G2_B; \
        uint4 t0, t1; \
        t0.x = packh2(pB00.x, pB10.x); t0.y = packh2(pB00.y, pB10.y); \
        t0.z = packh2(pB00.z, pB10.z); t0.w = packh2(pB00.w, pB10.w); \
        t1.x = packh2(pB01.x, pB11.x); t1.y = packh2(pB01.y, pB11.y); \
        t1.z = packh2(pB01.z, pB11.z); t1.w = packh2(pB01.w, pB11.w); \
        *(uint4*)(B_ + kp * 136 + nb8)     = t0; \
        *(uint4*)(B_ + kp * 136 + nb8 + 4) = t1; \
    } while (0)

    float acc[2][8][4];
#pragma unroll
    for (int i = 0; i < 2; i++)
#pragma unroll
        for (int j = 0; j < 8; j++)
#pragma unroll
            for (int q = 0; q < 4; q++) acc[i][j][q] = 0.f;

    G2_LD(0); G2_ST(0); G2_LD(1);
    __syncthreads();

    for (int c = 0; c < NCH2; c++) {
        if (c + 1 < NCH2) G2_ST((c + 1) % 3);
        if (c + 2 < NCH2) G2_LD(c + 2);
        __syncthreads();
        const uint32_t* A_ = sm + (c % 3) * G2_STG;
        const uint32_t* B_ = A_ + G2_B;
#pragma unroll
        for (int s = 0; s < 2; s++) {
            uint32_t af[2][4];
#pragma unroll
            for (int mt = 0; mt < 2; mt++) {
                int r = wm + mt * 16 + gid;
                af[mt][0] = A_[r * 20 + s * 8 + t4];
                af[mt][1] = A_[(r + 8) * 20 + s * 8 + t4];
                af[mt][2] = A_[r * 20 + s * 8 + t4 + 4];
                af[mt][3] = A_[(r + 8) * 20 + s * 8 + t4 + 4];
            }
#pragma unroll
            for (int nt = 0; nt < 8; nt++) {
                int cidx = wn + nt * 8 + gid;
                uint32_t bf[2] = { B_[(s * 8 + t4) * 136 + cidx], B_[(s * 8 + t4 + 4) * 136 + cidx] };
#pragma unroll
                for (int mt = 0; mt < 2; mt++) mma_f16(acc[mt][nt], af[mt], bf);
            }
        }
    }

#pragma unroll
    for (int mt = 0; mt < 2; mt++) {
#pragma unroll
        for (int nt = 0; nt < 8; nt++) {
            int col = n0 + wn + nt * 8 + t4 * 2;
#pragma unroll
            for (int h = 0; h < 2; h++) {
                int gm = m0 + wm + mt * 16 + gid + h * 8;
                if (gm < cnt) {
                    float wt = d_wt[base + gm];
                    float2 r;
                    r.x = acc[mt][nt][h * 2] * wt;
                    r.y = acc[mt][nt][h * 2 + 1] * wt;
                    *(float2*)(d_yscr + (size_t)(base + gm) * HDIM + col) = r;
                }
            }
        }
    }
#undef G2_LD
#undef G2_ST
}

// ---------------- kernel 6: combine ----------------
__global__ void k_combine(float* __restrict__ out) {
    const int t = blockIdx.x;
    const int s0 = d_slot[2 * t];
    const int s1 = d_slot[2 * t + 1];
    const float* y0 = d_yscr + (size_t)s0 * HDIM;
    const float* y1 = d_yscr + (size_t)s1 * HDIM;
    float* o = out + (size_t)t * HDIM;
    for (int h = threadIdx.x; h < HDIM; h += 256) o[h] = y0[h] + y1[h];
}

// ---------------- launch ----------------
extern "C" void kernel_launch(void* const* d_in, const int* in_sizes, int n_in,
                              void* d_out, int out_size) {
    const float* x    = (const float*)d_in[0];
    const float* Wg   = (const float*)d_in[1];
    const float* Win  = (const float*)d_in[2];
    const float* Wv   = (const float*)d_in[3];
    const float* Wout = (const float*)d_in[4];
    float* out = (float*)d_out;

    float* logits = nullptr;
    if (out_size >= (int)((size_t)T_TOKENS * HDIM + (size_t)T_TOKENS * NEXP))
        logits = out + (size_t)T_TOKENS * HDIM;

    cudaFuncSetAttribute(k_gemm1, cudaFuncAttributeMaxDynamicSharedMemorySize, SM1_BYTES);
    cudaFuncSetAttribute(k_gemm2, cudaFuncAttributeMaxDynamicSharedMemorySize, SM2_BYTES);

    k_zero<<<1, 32>>>();
    k_router<<<T_TOKENS, 256>>>(x, Wg, logits);
    k_scan<<<1, 1>>>();
    k_scatter<<<NPAIR / 256, 256>>>();

    dim3 g1(IDIM / 64, (T_TOKENS + 127) / 128, NEXP);
    k_gemm1<<<g1, 256, SM1_BYTES>>>(x, Win, Wv);

    dim3 g2(HDIM / 128, (T_TOKENS + 127) / 128, NEXP);
    k_gemm2<<<g2, 256, SM2_BYTES>>>(Wout);

    k_combine<<<T_TOKENS, 256>>>(out);
}